// round 16
// baseline (speedup 1.0000x reference)
#include <cuda_runtime.h>
#include <cuda_fp16.h>
#include <math.h>

#define B_    256
#define M_    256
#define A_    33
#define NH_   3
#define NOUT_ 100
#define FIN_  66
#define OBS_  17666
#define D2_   76900      // 100 + 3*256*100
#define D2P   77248      // 142 * 544
#define H2_   128
#define KSPL  142
#define NEG_BIG (-9e15f)
#define ATT_S   1024.f
#define INV_ATT 9.765625e-4f
#define W2_S    256.f
#define INV_W2  3.90625e-3f

// ---------------- scratch ----------------
__device__ __half  g_Wb[2][(size_t)NH_*B_*M_*104];  // Wh fp16 planes [h][b][j][104]
__device__ __half  g_xb[2][(size_t)B_*D2P];         // x fp16 planes  [b][k]
__device__ __half  g_W2b[2][(size_t)D2P*H2_];       // W2*256 fp16 planes [k][n]
__device__ float    g_e1[NH_*B_*M_];
__device__ float    g_e2[NH_*B_*M_];
__device__ float    g_F[NH_*B_*M_];
__device__ float    g_G2[NH_*B_*M_];
__device__ float    g_E1[NH_*B_*M_];
__device__ float    g_G1[NH_*B_*M_];
__device__ float    g_feats[(size_t)B_*M_*NH_*NOUT_];
__device__ float    g_hpart[(size_t)KSPL*B_*H2_];
__device__ float    g_hidT[H2_*B_];
__device__ unsigned g_adjb[M_*8];

// ---------------- f32x2 helpers ----------------
__device__ __forceinline__ unsigned long long splat2(float x){
    unsigned long long r; asm("mov.b64 %0, {%1,%1};" : "=l"(r) : "f"(x)); return r;
}
__device__ __forceinline__ void fma2(unsigned long long& d, unsigned long long a, unsigned long long b){
    asm("fma.rn.f32x2 %0, %1, %2, %0;" : "+l"(d) : "l"(a), "l"(b));
}
__device__ __forceinline__ void unpk(unsigned long long v, float& a, float& b){
    asm("mov.b64 {%0,%1}, %2;" : "=f"(a), "=f"(b) : "l"(v));
}
__device__ __forceinline__ unsigned s2u(const void* p){
    return (unsigned)__cvta_generic_to_shared(p);
}
__device__ __forceinline__ void lds_v2u64(unsigned p, unsigned long long& a, unsigned long long& b){
    asm("ld.shared.v2.u64 {%0,%1}, [%2];" : "=l"(a), "=l"(b) : "r"(p));
}
__device__ __forceinline__ unsigned long long lds_u64(unsigned p){
    unsigned long long a; asm("ld.shared.b64 %0, [%1];" : "=l"(a) : "r"(p)); return a;
}

// ---------------- cp.async ----------------
__device__ __forceinline__ void cp16(unsigned dst, const void* src){
    asm volatile("cp.async.ca.shared.global [%0], [%1], 16;" :: "r"(dst), "l"(src));
}
__device__ __forceinline__ void cp8(unsigned dst, const void* src){
    asm volatile("cp.async.ca.shared.global [%0], [%1], 8;" :: "r"(dst), "l"(src));
}
__device__ __forceinline__ void cp_commit(){
    asm volatile("cp.async.commit_group;" ::: "memory");
}
template<int N> __device__ __forceinline__ void cp_wait(){
    asm volatile("cp.async.wait_group %0;" :: "n"(N) : "memory");
}

// ---------------- mma.sync helpers (fp16 in, f32 acc) ----------------
__device__ __forceinline__ void ldsm4(unsigned* r, unsigned a){
    asm volatile("ldmatrix.sync.aligned.m8n8.x4.shared.b16 {%0,%1,%2,%3}, [%4];"
        : "=r"(r[0]), "=r"(r[1]), "=r"(r[2]), "=r"(r[3]) : "r"(a));
}
__device__ __forceinline__ void ldsm4t(unsigned* r, unsigned a){
    asm volatile("ldmatrix.sync.aligned.m8n8.x4.trans.shared.b16 {%0,%1,%2,%3}, [%4];"
        : "=r"(r[0]), "=r"(r[1]), "=r"(r[2]), "=r"(r[3]) : "r"(a));
}
__device__ __forceinline__ void ldsm2t(unsigned& r0, unsigned& r1, unsigned a){
    asm volatile("ldmatrix.sync.aligned.m8n8.x2.trans.shared.b16 {%0,%1}, [%2];"
        : "=r"(r0), "=r"(r1) : "r"(a));
}
__device__ __forceinline__ void mma16816(float* c, const unsigned* a, unsigned b0, unsigned b1){
    asm volatile("mma.sync.aligned.m16n8k16.row.col.f32.f16.f16.f32 "
        "{%0,%1,%2,%3}, {%4,%5,%6,%7}, {%8,%9}, {%0,%1,%2,%3};"
        : "+f"(c[0]), "+f"(c[1]), "+f"(c[2]), "+f"(c[3])
        : "r"(a[0]), "r"(a[1]), "r"(a[2]), "r"(a[3]), "r"(b0), "r"(b1));
}

// fp16 2-way split
__device__ __forceinline__ void hsplit(float v, __half& h, __half& l){
    h = __float2half_rn(v);
    l = __float2half_rn(v - __half2float(h));
}
__device__ __forceinline__ unsigned pack2h(__half a, __half b){
    __half2 t(a, b);
    return *(unsigned*)&t;
}

// ---------------- k0: adjacency -> bitmask ----------------
__global__ void k0_adjbits(const int* __restrict__ adj){
    int i = blockIdx.x, j = threadIdx.x;
    unsigned m = __ballot_sync(0xffffffffu, adj[i*M_ + j] > 0);
    if ((j & 31) == 0) g_adjb[i*8 + (j >> 5)] = m;
}

// ---------------- k_w2s: split W2*256 into 2 fp16 planes ----------------
__global__ __launch_bounds__(256) void k_w2s(const float* __restrict__ W2){
    size_t i = ((size_t)blockIdx.x*256 + threadIdx.x)*4;
    if (i >= (size_t)D2P*H2_) return;
    float4 v;
    if ((i >> 7) < D2_) v = *(const float4*)&W2[i];
    else v = make_float4(0.f, 0.f, 0.f, 0.f);
    __half h0,l0,h1,l1,h2,l2,h3,l3;
    hsplit(v.x*W2_S,h0,l0); hsplit(v.y*W2_S,h1,l1);
    hsplit(v.z*W2_S,h2,l2); hsplit(v.w*W2_S,h3,l3);
    uint2 sh; sh.x = pack2h(h0,h1); sh.y = pack2h(h2,h3);
    uint2 sl; sl.x = pack2h(l0,l1); sl.y = pack2h(l2,l3);
    *(uint2*)&g_W2b[0][i] = sh;
    *(uint2*)&g_W2b[1][i] = sl;
}

// ---------------- k1: Wh (fp16 planes) + e1/e2 ----------------
__global__ __launch_bounds__(256) void k1_wh(const float* __restrict__ obs,
                                             const float* __restrict__ Wg,
                                             const float* __restrict__ ag){
    __shared__ __align__(16) float Ws[FIN_*NOUT_];
    __shared__ __align__(16) float a1s[128], a2s[128];
    int b = blockIdx.x, h = blockIdx.y, m = threadIdx.x;
    for (int i = threadIdx.x; i < FIN_*NOUT_; i += 256) Ws[i] = Wg[h*FIN_*NOUT_ + i];
    if (threadIdx.x < 100)       a1s[threadIdx.x]       = ag[h*200 + threadIdx.x];
    else if (threadIdx.x < 200)  a2s[threadIdx.x - 100] = ag[h*200 + threadIdx.x];

    const float* ob = obs + (size_t)b*OBS_;
    float fr[FIN_];
    fr[0] = ob[770  + m];
    fr[1] = ob[1026 + m];
    {
        const float2* r2 = (const float2*)(ob + 1282 + m*32);
        const float2* i2 = (const float2*)(ob + 9474 + m*32);
        #pragma unroll
        for (int s = 0; s < 16; s++){ float2 v = r2[s]; fr[2 + 2*s] = v.x; fr[3 + 2*s] = v.y; }
        #pragma unroll
        for (int s = 0; s < 16; s++){ float2 v = i2[s]; fr[34 + 2*s] = v.x; fr[35 + 2*s] = v.y; }
    }
    __syncthreads();

    unsigned wsu = s2u(Ws), a1u = s2u(a1s), a2u = s2u(a2s);
    int hb = h*B_ + b;
    size_t rowb = ((size_t)hb*M_ + m)*104;
    unsigned long long e1p = 0ull, e2p = 0ull;
    for (int o = 0; o < NOUT_; o += 4){
        unsigned long long c0 = 0ull, c1 = 0ull;
        unsigned p = wsu + o*4;
        #pragma unroll
        for (int f = 0; f < FIN_; f++){
            unsigned long long w0, w1; lds_v2u64(p + f*400, w0, w1);
            unsigned long long xv = splat2(fr[f]);
            fma2(c0, xv, w0); fma2(c1, xv, w1);
        }
        float f0,f1,f2,f3;
        unpk(c0, f0, f1); unpk(c1, f2, f3);
        __half h0,l0,h1,l1,h2,l2,h3,l3;
        hsplit(f0,h0,l0); hsplit(f1,h1,l1);
        hsplit(f2,h2,l2); hsplit(f3,h3,l3);
        uint2 sh; sh.x = pack2h(h0,h1); sh.y = pack2h(h2,h3);
        uint2 sl; sl.x = pack2h(l0,l1); sl.y = pack2h(l2,l3);
        *(uint2*)&g_Wb[0][rowb + o] = sh;
        *(uint2*)&g_Wb[1][rowb + o] = sl;
        fma2(e1p, c0, lds_u64(a1u + o*4));  fma2(e1p, c1, lds_u64(a1u + o*4 + 8));
        fma2(e2p, c0, lds_u64(a2u + o*4));  fma2(e2p, c1, lds_u64(a2u + o*4 + 8));
    }
    uint2 z; z.x = 0u; z.y = 0u;
    *(uint2*)&g_Wb[0][rowb + 100] = z;
    *(uint2*)&g_Wb[1][rowb + 100] = z;
    { float x, y; unpk(e1p, x, y); g_e1[hb*M_ + m] = x + y;
      unpk(e2p, x, y);             g_e2[hb*M_ + m] = x + y; }
}

// ---------------- k1b: softmax stats, exp-factorized ----------------
__global__ __launch_bounds__(512) void k1b_stats(){
    __shared__ float e1s[256];
    __shared__ unsigned adjs[2048];
    __shared__ float pmx[512], pA[512], pN[512];
    __shared__ float E1s[256], G1s[256];
    __shared__ float red8[8];
    int b = blockIdx.x, h = blockIdx.y, tid = threadIdx.x;
    int hb = h*B_ + b;
    if (tid < 256) e1s[tid] = g_e1[hb*M_ + tid];
    for (int i = tid; i < 2048; i += 512) adjs[i] = g_adjb[i];
    __syncthreads();

    int j = tid & 255, ih = tid >> 8;
    int w5 = j >> 5, bp = j & 31;
    float e2v = g_e2[hb*M_ + j];

    float mx = NEG_BIG;
    for (int i = ih*128; i < ih*128 + 128; i++){
        float v = e1s[i] + e2v; v = fmaxf(v, 0.01f*v);
        bool on = (adjs[i*8 + w5] >> bp) & 1u;
        mx = fmaxf(mx, on ? v : NEG_BIG);
    }
    pmx[tid] = mx;
    if (tid < 256){
        float v = e1s[tid];
        #pragma unroll
        for (int o = 16; o; o >>= 1) v = fmaxf(v, __shfl_xor_sync(0xffffffffu, v, o));
        if ((tid & 31) == 0) red8[tid >> 5] = v;
    }
    __syncthreads();
    mx = fmaxf(pmx[j], pmx[j + 256]);
    float mxe1 = red8[0];
    #pragma unroll
    for (int q = 1; q < 8; q++) mxe1 = fmaxf(mxe1, red8[q]);
    if (tid < 256){
        E1s[tid] = __expf(e1s[tid] - mxe1);
        G1s[tid] = __expf(0.01f * e1s[tid]);
    }
    __syncthreads();

    float aP = 0.f, aN = 0.f;
    for (int i = ih*128; i < ih*128 + 128; i++){
        float v = e1s[i] + e2v;
        bool on = (adjs[i*8 + w5] >> bp) & 1u;
        if (on){
            if (v >= 0.f) aP += E1s[i];
            else          aN += G1s[i];
        }
    }
    pA[tid] = aP; pN[tid] = aN;
    __syncthreads();

    if (ih == 0){
        float accP = pA[j] + pA[j + 256];
        float accN = pN[j] + pN[j + 256];
        float Fr = __expf(e2v + mxe1 - mx);
        float Gr = __expf(0.01f*e2v - mx);
        float rs = 1.f / (accP*Fr + accN*Gr);
        g_F[hb*M_ + j]  = Fr*rs*ATT_S;
        g_G2[hb*M_ + j] = Gr*rs*ATT_S;
    }
    if (tid < 256){
        g_E1[hb*M_ + tid] = E1s[tid];
        g_G1[hb*M_ + tid] = G1s[tid];
    }
}

// ---------------- k2m: HMMA attention GEMM, dbl-buffered att+B, wait->sync->compute ----------------
#define OFF_A    0          // 2 att bufs x (2 planes x 5120) = 20480
#define OFF_B    20480      // 2 B bufs x (2 planes x 6656) = 26624
#define OFF_E1   47104      // 64 f32
#define OFF_E2   47360      // 256 f32
#define OFF_F    48384
#define OFF_G2   49408
#define OFF_XE1  50432      // 64 f32
#define OFF_XG1  50688      // 64 f32
#define OFF_ADJ  50944      // 512 u32
#define K2M_SMEM 52992

extern __shared__ char smm[];
__global__ __launch_bounds__(128, 4) void k2m(){
    const int b = blockIdx.x, h = blockIdx.y, ih = blockIdx.z;
    const int tid = threadIdx.x, wid = tid >> 5, lid = tid & 31;
    const int hb = h*B_ + b;
    char* sb = smm;
    unsigned sbu = s2u(smm);

    float*    e1s  = (float*)(sb + OFF_E1);
    float*    e2s  = (float*)(sb + OFF_E2);
    float*    Fs   = (float*)(sb + OFF_F);
    float*    G2s  = (float*)(sb + OFF_G2);
    float*    E1r  = (float*)(sb + OFF_XE1);
    float*    G1r  = (float*)(sb + OFF_XG1);
    unsigned* adjs = (unsigned*)(sb + OFF_ADJ);

    if (tid < 64){
        e1s[tid] = g_e1[hb*M_ + ih*64 + tid];
        E1r[tid] = g_E1[hb*M_ + ih*64 + tid];
        G1r[tid] = g_G1[hb*M_ + ih*64 + tid];
    }
    { int t2 = tid*2;
      e2s[t2] = g_e2[hb*M_ + t2];  e2s[t2+1] = g_e2[hb*M_ + t2+1];
      Fs[t2]  = g_F[hb*M_ + t2];   Fs[t2+1]  = g_F[hb*M_ + t2+1];
      G2s[t2] = g_G2[hb*M_ + t2];  G2s[t2+1] = g_G2[hb*M_ + t2+1]; }
    for (int i = tid; i < 512; i += 128) adjs[i] = g_adjb[ih*512 + i];

    const size_t plane_stride = (size_t)NH_*B_*M_*104*2;
    auto cpB = [&](int c, int buf){
        const char* src = (const char*)&g_Wb[0][((size_t)hb*M_ + c*32)*104];
        unsigned dbase = sbu + OFF_B + buf*13312;
        for (int idx = tid; idx < 832; idx += 128){
            int p = idx / 416, e = idx - p*416;
            cp16(dbase + p*6656 + e*16, src + p*plane_stride + e*16);
        }
        cp_commit();
    };

    cpB(0, 0);
    __syncthreads();   // scalars visible for att staging

    const int mg = wid >> 1, nh = wid & 1;
    const int colb = nh ? 56 : 0;
    const int il = tid >> 1, jb = (tid & 1) * 16;
    const float e1v = e1s[il];
    const float E1i = E1r[il];
    const float G1i = G1r[il];

    auto stage_att = [&](int c, int buf){
        unsigned arow = adjs[il*8 + c];
        unsigned abase = (unsigned)(buf*10240) + (unsigned)(il*40 + jb)*2;
        const int j0 = c*32;
        #pragma unroll
        for (int q = 0; q < 16; q += 2){
            int jg = j0 + jb + q;
            float v0 = e1v + e2s[jg];
            float v1 = e1v + e2s[jg+1];
            float p0 = (v0 >= 0.f) ? E1i*Fs[jg]   : G1i*G2s[jg];
            float p1 = (v1 >= 0.f) ? E1i*Fs[jg+1] : G1i*G2s[jg+1];
            float a0 = ((arow >> (jb+q))   & 1u) ? p0 : 0.f;
            float a1 = ((arow >> (jb+q+1)) & 1u) ? p1 : 0.f;
            __half h0,l0,h1,l1;
            hsplit(a0, h0, l0); hsplit(a1, h1, l1);
            *(unsigned*)(sb + OFF_A + abase + q*2)        = pack2h(h0, h1);
            *(unsigned*)(sb + OFF_A + abase + 5120 + q*2) = pack2h(l0, l1);
        }
    };

    stage_att(0, 0);

    float acc[2][7][4];
    #pragma unroll
    for (int mt = 0; mt < 2; mt++)
        #pragma unroll
        for (int nt = 0; nt < 7; nt++){
            acc[mt][nt][0]=0.f; acc[mt][nt][1]=0.f; acc[mt][nt][2]=0.f; acc[mt][nt][3]=0.f;
        }

    for (int c = 0; c < 8; c++){
        // stage next chunk (att smem-writes + B cp.async), then wait+sync for current
        if (c < 7){
            stage_att(c + 1, (c + 1) & 1);
            cpB(c + 1, (c + 1) & 1);
            cp_wait<1>();
        } else {
            cp_wait<0>();
        }
        __syncthreads();   // collective: B(c) copies + att(c) stores visible to all

        unsigned abufu = sbu + OFF_A + (c&1)*10240;
        unsigned bufu  = sbu + OFF_B + (c&1)*13312;
        #pragma unroll
        for (int ks = 0; ks < 2; ks++){
            unsigned af[2][2][4];
            #pragma unroll
            for (int pa = 0; pa < 2; pa++)
                #pragma unroll
                for (int mt = 0; mt < 2; mt++){
                    unsigned addr = abufu + pa*5120
                        + (unsigned)((mg*32 + mt*16 + (lid & 15))*40 + ks*16 + (lid >> 4)*8)*2;
                    ldsm4(af[pa][mt], addr);
                }
            unsigned krow = (unsigned)(ks*16 + (lid & 15))*104;
            #pragma unroll
            for (int pb = 0; pb < 2; pb++){
                const int NPA = 2 - pb;
                unsigned bbp = bufu + pb*6656;
                #pragma unroll
                for (int g = 0; g < 3; g++){
                    unsigned r[4];
                    ldsm4t(r, bbp + (krow + colb + g*16 + (lid >> 4)*8)*2);
                    #pragma unroll
                    for (int pa = 0; pa < 2; pa++){
                        if (pa < NPA){
                            #pragma unroll
                            for (int mt = 0; mt < 2; mt++){
                                mma16816(acc[mt][2*g],     af[pa][mt], r[0], r[1]);
                                mma16816(acc[mt][2*g + 1], af[pa][mt], r[2], r[3]);
                            }
                        }
                    }
                }
                if (!nh){
                    unsigned r0, r1;
                    ldsm2t(r0, r1, bbp + (krow + 48)*2);
                    #pragma unroll
                    for (int pa = 0; pa < 2; pa++){
                        if (pa < NPA){
                            #pragma unroll
                            for (int mt = 0; mt < 2; mt++)
                                mma16816(acc[mt][6], af[pa][mt], r0, r1);
                        }
                    }
                }
            }
        }
        __syncthreads();   // all reads of buffers (c) done before next-iter staging overwrites
    }

    // epilogue: unscale + elu -> g_feats
    const int NT = nh ? 6 : 7;
    int gr = lid >> 2, tg = lid & 3;
    #pragma unroll
    for (int mt = 0; mt < 2; mt++){
        size_t mrow = (size_t)b*M_ + ih*64 + mg*32 + mt*16 + gr;
        float* d0 = g_feats + mrow*300 + h*100;
        float* d1 = d0 + (size_t)8*300;
        #pragma unroll
        for (int nt = 0; nt < 7; nt++){
            if (nt >= NT) break;
            int n = colb + nt*8 + tg*2;
            if (n < 100){
                float v0 = acc[mt][nt][0]*INV_ATT; v0 = v0 > 0.f ? v0 : expm1f(v0);
                float v1 = acc[mt][nt][1]*INV_ATT; v1 = v1 > 0.f ? v1 : expm1f(v1);
                float v2 = acc[mt][nt][2]*INV_ATT; v2 = v2 > 0.f ? v2 : expm1f(v2);
                float v3 = acc[mt][nt][3]*INV_ATT; v3 = v3 > 0.f ? v3 : expm1f(v3);
                float2 p0; p0.x = v0; p0.y = v1;
                float2 p1; p1.x = v2; p1.y = v3;
                *(float2*)(d0 + n) = p0;
                *(float2*)(d1 + n) = p1;
            }
        }
    }
}

// ---------------- k3: LayerNorm(300) + elu -> x fp16 planes ----------------
__global__ __launch_bounds__(256) void k3_ln(const float* __restrict__ lnw,
                                             const float* __restrict__ lnb){
    int wid = threadIdx.x >> 5, lane = threadIdx.x & 31;
    int row = blockIdx.x*8 + wid;
    const float* xr = g_feats + (size_t)row*300;
    float v[10]; float s = 0.f;
    #pragma unroll
    for (int i = 0; i < 10; i++){
        int c = lane + i*32;
        v[i] = (c < 300) ? xr[c] : 0.f;
        s += v[i];
    }
    #pragma unroll
    for (int o = 16; o; o >>= 1) s += __shfl_xor_sync(0xffffffffu, s, o);
    float mu = s * (1.f/300.f);
    float q = 0.f;
    #pragma unroll
    for (int i = 0; i < 10; i++){
        int c = lane + i*32;
        if (c < 300){ float d = v[i] - mu; q = fmaf(d, d, q); }
    }
    #pragma unroll
    for (int o = 16; o; o >>= 1) q += __shfl_xor_sync(0xffffffffu, q, o);
    float rsv = rsqrtf(q*(1.f/300.f) + 1e-5f);
    int bb = row >> 8, mm = row & 255;
    size_t base = (size_t)bb*D2P + 100 + (size_t)mm*300;
    #pragma unroll
    for (int i = 0; i < 10; i++){
        int c = lane + i*32;
        if (c < 300){
            float t = (v[i] - mu)*rsv*__ldg(&lnw[c]) + __ldg(&lnb[c]);
            t = t > 0.f ? t : expm1f(t);
            __half th, tl; hsplit(t, th, tl);
            g_xb[0][base + c] = th;
            g_xb[1][base + c] = tl;
        }
    }
}

// ---------------- k3b: server_feat = relu(ss@W1 + b1), split-k ----------------
__global__ __launch_bounds__(256) void k3b_sfeat(const float* __restrict__ obs,
                                                 const float* __restrict__ W1,
                                                 const float* __restrict__ b1){
    __shared__ float ss[772];
    __shared__ float part[256];
    int b = blockIdx.x, tid = threadIdx.x;
    for (int i = tid; i < 770; i += 256) ss[i] = obs[(size_t)b*OBS_ + i];
    __syncthreads();
    if (tid < 200){
        int o = tid % 100, hf = tid / 100;
        int k0 = hf*385, k1 = k0 + 385;
        float a0=0.f,a1=0.f,a2=0.f,a3=0.f;
        int k = k0;
        for (; k + 4 <= k1; k += 4){
            a0 = fmaf(ss[k],   __ldg(&W1[(k)*100 + o]),   a0);
            a1 = fmaf(ss[k+1], __ldg(&W1[(k+1)*100 + o]), a1);
            a2 = fmaf(ss[k+2], __ldg(&W1[(k+2)*100 + o]), a2);
            a3 = fmaf(ss[k+3], __ldg(&W1[(k+3)*100 + o]), a3);
        }
        for (; k < k1; k++) a0 = fmaf(ss[k], __ldg(&W1[k*100 + o]), a0);
        part[tid] = (a0 + a1) + (a2 + a3);
    }
    __syncthreads();
    if (tid < 100){
        float t = fmaxf(part[tid] + part[tid + 100] + b1[tid], 0.f);
        __half th, tl; hsplit(t, th, tl);
        size_t base = (size_t)b*D2P + tid;
        g_xb[0][base] = th;
        g_xb[1][base] = tl;
    }
}

// ---------------- k4h: HMMA split-K GEMM, 3-stage pipeline, 1 sync/stage ----------------
#define K4H_SMEM 113664
extern __shared__ char sk4[];
__global__ __launch_bounds__(256, 2) void k4h(){
    const int kz = blockIdx.x, by = blockIdx.y;
    const int b0 = by*128;
    const int tid = threadIdx.x, wid = tid >> 5, lid = tid & 31;
    unsigned sbu = s2u(sk4);
    const int kbase = kz*544;

    const int m0 = (wid >> 1)*32, n0 = (wid & 1)*64;
    float acc[2][8][4];
    #pragma unroll
    for (int mt = 0; mt < 2; mt++)
        #pragma unroll
        for (int nt = 0; nt < 8; nt++){
            acc[mt][nt][0]=0.f; acc[mt][nt][1]=0.f; acc[mt][nt][2]=0.f; acc[mt][nt][3]=0.f;
        }

    auto stage = [&](int buf, int s){
        int kg = kbase + s*32;
        unsigned ab = sbu + buf*20480;
        #pragma unroll
        for (int i = 0; i < 8; i++){
            int q = tid + i*256;
            int p = q >> 10, rem = q & 1023;
            int row = rem >> 3, seg = rem & 7;
            cp8(ab + p*10240 + row*80 + seg*8,
                &g_xb[p][(size_t)(b0 + row)*D2P + kg + seg*4]);
        }
        unsigned bb = sbu + 61440 + buf*17408;
        #pragma unroll
        for (int i = 0; i < 4; i++){
            int q = tid + i*256;
            int p = q >> 9, rem = q & 511;
            int row = rem >> 4, seg = rem & 15;
            cp16(bb + p*8704 + row*272 + seg*16,
                 &g_W2b[p][(size_t)(kg + row)*H2_ + seg*8]);
        }
        cp_commit();
    };

    stage(0, 0);
    stage(1, 1);

    const int r4r = lid >> 2, c2 = (lid & 3)*2;
    int bufc = 0;
    for (int s = 0; s < 17; s++){
        if (s < 16) cp_wait<1>();
        else        cp_wait<0>();
        __syncthreads();
        if (s + 2 < 17){
            int nb = bufc + 2; if (nb >= 3) nb -= 3;
            stage(nb, s + 2);
        }

        unsigned abuf = sbu + bufc*20480;
        unsigned bbuf = sbu + 61440 + bufc*17408;
        #pragma unroll
        for (int ks = 0; ks < 2; ks++){
            unsigned af[2][2][4];
            #pragma unroll
            for (int p = 0; p < 2; p++)
                #pragma unroll
                for (int mt = 0; mt < 2; mt++){
                    unsigned addr = abuf + p*10240
                        + (unsigned)((m0 + mt*16 + (lid & 15))*40 + ks*16 + (lid >> 4)*8)*2;
                    ldsm4(af[p][mt], addr);
                }
            unsigned krow = (unsigned)(ks*16 + (lid & 15))*272 + (unsigned)(n0 + (lid >> 4)*8)*2;
            #pragma unroll
            for (int pb = 0; pb < 2; pb++){
                const int NPA = 2 - pb;
                unsigned bb = bbuf + pb*8704 + krow;
                #pragma unroll
                for (int g = 0; g < 4; g++){
                    unsigned r[4];
                    ldsm4t(r, bb + g*32);
                    #pragma unroll
                    for (int pa = 0; pa < 2; pa++){
                        if (pa < NPA){
                            #pragma unroll
                            for (int mt = 0; mt < 2; mt++){
                                mma16816(acc[mt][2*g],     af[pa][mt], r[0], r[1]);
                                mma16816(acc[mt][2*g + 1], af[pa][mt], r[2], r[3]);
                            }
                        }
                    }
                }
            }
        }
        bufc++; if (bufc >= 3) bufc = 0;
    }

    #pragma unroll
    for (int mt = 0; mt < 2; mt++){
        int row0 = b0 + m0 + mt*16 + r4r;
        float* d0 = g_hpart + ((size_t)kz*B_ + row0)*H2_;
        float* d1 = d0 + (size_t)8*H2_;
        #pragma unroll
        for (int nt = 0; nt < 8; nt++){
            int n = n0 + nt*8 + c2;
            float2 p0; p0.x = acc[mt][nt][0]; p0.y = acc[mt][nt][1];
            float2 p1; p1.x = acc[mt][nt][2]; p1.y = acc[mt][nt][3];
            *(float2*)(d0 + n) = p0;
            *(float2*)(d1 + n) = p1;
        }
    }
}

// ---------------- k4b: split-K reduce + unscale + bias + relu ----------------
__global__ void k4b_reduce(const float* __restrict__ b2){
    int t = blockIdx.x*blockDim.x + threadIdx.x;
    if (t >= B_*H2_) return;
    int b = t >> 7, n = t & 127;
    float s = 0.f;
    for (int kz = 0; kz < KSPL; kz++) s += g_hpart[((size_t)kz*B_ + b)*H2_ + n];
    g_hidT[n*B_ + b] = fmaxf(s*INV_W2 + b2[n], 0.f);
}

// ---------------- k5: logits + gumbel + argmax + one-hot write ----------------
__global__ __launch_bounds__(256) void k5_logits(const float* __restrict__ Wout,
                                                 const float* __restrict__ bout,
                                                 const float* __restrict__ ug,
                                                 float* __restrict__ out){
    __shared__ __align__(16) float Wos[H2_*36];
    __shared__ float bos[A_];
    int mb = blockIdx.x, b = threadIdx.x;
    for (int i = threadIdx.x; i < H2_*36; i += 256){
        int hh = i / 36, aa = i - hh*36;
        Wos[i] = (aa < A_) ? Wout[(size_t)mb*H2_*A_ + hh*A_ + aa] : 0.f;
    }
    if (threadIdx.x < A_) bos[threadIdx.x] = bout[mb*A_ + threadIdx.x];
    __syncthreads();

    unsigned wou = s2u(Wos);
    unsigned long long acc[17];
    #pragma unroll
    for (int p = 0; p < 17; p++) acc[p] = 0ull;
    #pragma unroll 2
    for (int hh = 0; hh < H2_; hh++){
        float hv = g_hidT[hh*B_ + b];
        unsigned long long hs = splat2(hv);
        unsigned base = wou + hh*144;
        #pragma unroll
        for (int q = 0; q < 8; q++){
            unsigned long long w0, w1; lds_v2u64(base + q*16, w0, w1);
            fma2(acc[2*q],   hs, w0);
            fma2(acc[2*q+1], hs, w1);
        }
        fma2(acc[16], hs, lds_u64(base + 128));
    }

    const float* u = ug + ((size_t)b*M_ + mb)*A_;
    float best = -INFINITY; int bi = 0;
    #pragma unroll
    for (int p = 0; p < 17; p++){
        float va, vb; unpk(acc[p], va, vb);
        #pragma unroll
        for (int s = 0; s < 2; s++){
            int a = 2*p + s;
            if (a >= A_) break;
            float x = (s ? vb : va) + bos[a];
            float e = x > 0.f ? x : expm1f(x);
            float l = tanhf(e);
            float uu = fmaxf(__ldg(&u[a]), 1e-10f);
            float g = -logf(-logf(uu));
            float z = l + g;
            if (z > best){ best = z; bi = a; }
        }
    }
    float* orow = out + ((size_t)b*M_ + mb)*A_;
    #pragma unroll
    for (int a = 0; a < A_; a++) orow[a] = (a == bi) ? 1.f : 0.f;
}

extern "C" void kernel_launch(void* const* d_in, const int* in_sizes, int n_in,
                              void* d_out, int out_size){
    const float* obs  = (const float*)d_in[0];
    const int*   adj  = (const int*)  d_in[1];
    const float* ug   = (const float*)d_in[2];
    const float* Wg   = (const float*)d_in[3];
    const float* ag   = (const float*)d_in[4];
    const float* lnw  = (const float*)d_in[5];
    const float* lnb  = (const float*)d_in[6];
    const float* W1   = (const float*)d_in[7];
    const float* b1   = (const float*)d_in[8];
    const float* W2   = (const float*)d_in[9];
    const float* b2   = (const float*)d_in[10];
    const float* Wout = (const float*)d_in[11];
    const float* bout = (const float*)d_in[12];
    float* out = (float*)d_out;

    k0_adjbits<<<M_, 256>>>(adj);
    k_w2s<<<(int)(((size_t)D2P*H2_/4 + 255)/256), 256>>>(W2);
    k1_wh<<<dim3(B_, NH_), 256>>>(obs, Wg, ag);
    k1b_stats<<<dim3(B_, NH_), 512>>>();

    cudaFuncSetAttribute(k2m, cudaFuncAttributeMaxDynamicSharedMemorySize, K2M_SMEM);
    k2m<<<dim3(B_, NH_, 4), 128, K2M_SMEM>>>();

    k3b_sfeat<<<B_, 256>>>(obs, W1, b1);
    k3_ln<<<(B_*M_)/8, 256>>>(lnw, lnb);

    cudaFuncSetAttribute(k4h, cudaFuncAttributeMaxDynamicSharedMemorySize, K4H_SMEM);
    k4h<<<dim3(KSPL, 2), 256, K4H_SMEM>>>();

    k4b_reduce<<<(B_*H2_ + 255)/256, 256>>>(b2);
    k5_logits<<<M_, 256>>>(Wout, bout, ug, out);
}

// round 17
// speedup vs baseline: 1.0637x; 1.0637x over previous
#include <cuda_runtime.h>
#include <cuda_fp16.h>
#include <math.h>

#define B_    256
#define M_    256
#define A_    33
#define NH_   3
#define NOUT_ 100
#define FIN_  66
#define OBS_  17666
#define D2_   76900      // 100 + 3*256*100
#define D2P   77248      // 142 * 544
#define H2_   128
#define KSPL  142
#define NEG_BIG (-9e15f)
#define ATT_S   1024.f
#define INV_ATT 9.765625e-4f
#define W2_S    256.f
#define INV_W2  3.90625e-3f

// ---------------- scratch ----------------
__device__ __half  g_Wb[2][(size_t)NH_*B_*M_*104];  // Wh fp16 planes [h][b][j][104]
__device__ __half  g_xb[2][(size_t)B_*D2P];         // x fp16 planes  [b][k]
__device__ __half  g_W2b[2][(size_t)D2P*H2_];       // W2*256 fp16 planes [k][n]
__device__ float    g_e1[NH_*B_*M_];
__device__ float    g_e2[NH_*B_*M_];
__device__ float    g_F[NH_*B_*M_];
__device__ float    g_G2[NH_*B_*M_];
__device__ float    g_E1[NH_*B_*M_];
__device__ float    g_G1[NH_*B_*M_];
__device__ float    g_feats[(size_t)B_*M_*NH_*NOUT_];
__device__ float    g_hpart[(size_t)KSPL*B_*H2_];
__device__ float    g_hidT[H2_*B_];
__device__ unsigned g_adjb[M_*8];

// ---------------- f32x2 helpers ----------------
__device__ __forceinline__ unsigned long long splat2(float x){
    unsigned long long r; asm("mov.b64 %0, {%1,%1};" : "=l"(r) : "f"(x)); return r;
}
__device__ __forceinline__ void fma2(unsigned long long& d, unsigned long long a, unsigned long long b){
    asm("fma.rn.f32x2 %0, %1, %2, %0;" : "+l"(d) : "l"(a), "l"(b));
}
__device__ __forceinline__ void unpk(unsigned long long v, float& a, float& b){
    asm("mov.b64 {%0,%1}, %2;" : "=f"(a), "=f"(b) : "l"(v));
}
__device__ __forceinline__ unsigned s2u(const void* p){
    return (unsigned)__cvta_generic_to_shared(p);
}
__device__ __forceinline__ void lds_v2u64(unsigned p, unsigned long long& a, unsigned long long& b){
    asm("ld.shared.v2.u64 {%0,%1}, [%2];" : "=l"(a), "=l"(b) : "r"(p));
}
__device__ __forceinline__ unsigned long long lds_u64(unsigned p){
    unsigned long long a; asm("ld.shared.b64 %0, [%1];" : "=l"(a) : "r"(p)); return a;
}

// ---------------- cp.async ----------------
__device__ __forceinline__ void cp16(unsigned dst, const void* src){
    asm volatile("cp.async.ca.shared.global [%0], [%1], 16;" :: "r"(dst), "l"(src));
}
__device__ __forceinline__ void cp8(unsigned dst, const void* src){
    asm volatile("cp.async.ca.shared.global [%0], [%1], 8;" :: "r"(dst), "l"(src));
}
__device__ __forceinline__ void cp_commit(){
    asm volatile("cp.async.commit_group;" ::: "memory");
}
template<int N> __device__ __forceinline__ void cp_wait(){
    asm volatile("cp.async.wait_group %0;" :: "n"(N) : "memory");
}

// ---------------- mma.sync helpers (fp16 in, f32 acc) ----------------
__device__ __forceinline__ void ldsm4(unsigned* r, unsigned a){
    asm volatile("ldmatrix.sync.aligned.m8n8.x4.shared.b16 {%0,%1,%2,%3}, [%4];"
        : "=r"(r[0]), "=r"(r[1]), "=r"(r[2]), "=r"(r[3]) : "r"(a));
}
__device__ __forceinline__ void ldsm4t(unsigned* r, unsigned a){
    asm volatile("ldmatrix.sync.aligned.m8n8.x4.trans.shared.b16 {%0,%1,%2,%3}, [%4];"
        : "=r"(r[0]), "=r"(r[1]), "=r"(r[2]), "=r"(r[3]) : "r"(a));
}
__device__ __forceinline__ void ldsm2t(unsigned& r0, unsigned& r1, unsigned a){
    asm volatile("ldmatrix.sync.aligned.m8n8.x2.trans.shared.b16 {%0,%1}, [%2];"
        : "=r"(r0), "=r"(r1) : "r"(a));
}
__device__ __forceinline__ void mma16816(float* c, const unsigned* a, unsigned b0, unsigned b1){
    asm volatile("mma.sync.aligned.m16n8k16.row.col.f32.f16.f16.f32 "
        "{%0,%1,%2,%3}, {%4,%5,%6,%7}, {%8,%9}, {%0,%1,%2,%3};"
        : "+f"(c[0]), "+f"(c[1]), "+f"(c[2]), "+f"(c[3])
        : "r"(a[0]), "r"(a[1]), "r"(a[2]), "r"(a[3]), "r"(b0), "r"(b1));
}

// fp16 2-way split
__device__ __forceinline__ void hsplit(float v, __half& h, __half& l){
    h = __float2half_rn(v);
    l = __float2half_rn(v - __half2float(h));
}
__device__ __forceinline__ unsigned pack2h(__half a, __half b){
    __half2 t(a, b);
    return *(unsigned*)&t;
}

// ---------------- k0: adjacency -> bitmask ----------------
__global__ void k0_adjbits(const int* __restrict__ adj){
    int i = blockIdx.x, j = threadIdx.x;
    unsigned m = __ballot_sync(0xffffffffu, adj[i*M_ + j] > 0);
    if ((j & 31) == 0) g_adjb[i*8 + (j >> 5)] = m;
}

// ---------------- k_w2s: split W2*256 into 2 fp16 planes ----------------
__global__ __launch_bounds__(256) void k_w2s(const float* __restrict__ W2){
    size_t i = ((size_t)blockIdx.x*256 + threadIdx.x)*4;
    if (i >= (size_t)D2P*H2_) return;
    float4 v;
    if ((i >> 7) < D2_) v = *(const float4*)&W2[i];
    else v = make_float4(0.f, 0.f, 0.f, 0.f);
    __half h0,l0,h1,l1,h2,l2,h3,l3;
    hsplit(v.x*W2_S,h0,l0); hsplit(v.y*W2_S,h1,l1);
    hsplit(v.z*W2_S,h2,l2); hsplit(v.w*W2_S,h3,l3);
    uint2 sh; sh.x = pack2h(h0,h1); sh.y = pack2h(h2,h3);
    uint2 sl; sl.x = pack2h(l0,l1); sl.y = pack2h(l2,l3);
    *(uint2*)&g_W2b[0][i] = sh;
    *(uint2*)&g_W2b[1][i] = sl;
}

// ---------------- k1: Wh (fp16 planes) + e1/e2 ----------------
__global__ __launch_bounds__(256) void k1_wh(const float* __restrict__ obs,
                                             const float* __restrict__ Wg,
                                             const float* __restrict__ ag){
    __shared__ __align__(16) float Ws[FIN_*NOUT_];
    __shared__ __align__(16) float a1s[128], a2s[128];
    int b = blockIdx.x, h = blockIdx.y, m = threadIdx.x;
    for (int i = threadIdx.x; i < FIN_*NOUT_; i += 256) Ws[i] = Wg[h*FIN_*NOUT_ + i];
    if (threadIdx.x < 100)       a1s[threadIdx.x]       = ag[h*200 + threadIdx.x];
    else if (threadIdx.x < 200)  a2s[threadIdx.x - 100] = ag[h*200 + threadIdx.x];

    const float* ob = obs + (size_t)b*OBS_;
    float fr[FIN_];
    fr[0] = ob[770  + m];
    fr[1] = ob[1026 + m];
    {
        const float2* r2 = (const float2*)(ob + 1282 + m*32);
        const float2* i2 = (const float2*)(ob + 9474 + m*32);
        #pragma unroll
        for (int s = 0; s < 16; s++){ float2 v = r2[s]; fr[2 + 2*s] = v.x; fr[3 + 2*s] = v.y; }
        #pragma unroll
        for (int s = 0; s < 16; s++){ float2 v = i2[s]; fr[34 + 2*s] = v.x; fr[35 + 2*s] = v.y; }
    }
    __syncthreads();

    unsigned wsu = s2u(Ws), a1u = s2u(a1s), a2u = s2u(a2s);
    int hb = h*B_ + b;
    size_t rowb = ((size_t)hb*M_ + m)*104;
    unsigned long long e1p = 0ull, e2p = 0ull;
    for (int o = 0; o < NOUT_; o += 4){
        unsigned long long c0 = 0ull, c1 = 0ull;
        unsigned p = wsu + o*4;
        #pragma unroll
        for (int f = 0; f < FIN_; f++){
            unsigned long long w0, w1; lds_v2u64(p + f*400, w0, w1);
            unsigned long long xv = splat2(fr[f]);
            fma2(c0, xv, w0); fma2(c1, xv, w1);
        }
        float f0,f1,f2,f3;
        unpk(c0, f0, f1); unpk(c1, f2, f3);
        __half h0,l0,h1,l1,h2,l2,h3,l3;
        hsplit(f0,h0,l0); hsplit(f1,h1,l1);
        hsplit(f2,h2,l2); hsplit(f3,h3,l3);
        uint2 sh; sh.x = pack2h(h0,h1); sh.y = pack2h(h2,h3);
        uint2 sl; sl.x = pack2h(l0,l1); sl.y = pack2h(l2,l3);
        *(uint2*)&g_Wb[0][rowb + o] = sh;
        *(uint2*)&g_Wb[1][rowb + o] = sl;
        fma2(e1p, c0, lds_u64(a1u + o*4));  fma2(e1p, c1, lds_u64(a1u + o*4 + 8));
        fma2(e2p, c0, lds_u64(a2u + o*4));  fma2(e2p, c1, lds_u64(a2u + o*4 + 8));
    }
    uint2 z; z.x = 0u; z.y = 0u;
    *(uint2*)&g_Wb[0][rowb + 100] = z;
    *(uint2*)&g_Wb[1][rowb + 100] = z;
    { float x, y; unpk(e1p, x, y); g_e1[hb*M_ + m] = x + y;
      unpk(e2p, x, y);             g_e2[hb*M_ + m] = x + y; }
}

// ---------------- k1b: softmax stats, exp-factorized, single masked pass ----------------
// mx cancels in softmax; use upper bound mx' = max(u, 0.01u), u = mxe1 + e2_j.
__global__ __launch_bounds__(512) void k1b_stats(){
    __shared__ float e1s[256];
    __shared__ unsigned adjs[2048];
    __shared__ float pA[512], pN[512];
    __shared__ float E1s[256], G1s[256];
    __shared__ float red8[8];
    int b = blockIdx.x, h = blockIdx.y, tid = threadIdx.x;
    int hb = h*B_ + b;
    if (tid < 256) e1s[tid] = g_e1[hb*M_ + tid];
    for (int i = tid; i < 2048; i += 512) adjs[i] = g_adjb[i];
    __syncthreads();

    if (tid < 256){
        float v = e1s[tid];
        #pragma unroll
        for (int o = 16; o; o >>= 1) v = fmaxf(v, __shfl_xor_sync(0xffffffffu, v, o));
        if ((tid & 31) == 0) red8[tid >> 5] = v;
    }
    __syncthreads();
    float mxe1 = red8[0];
    #pragma unroll
    for (int q = 1; q < 8; q++) mxe1 = fmaxf(mxe1, red8[q]);
    if (tid < 256){
        E1s[tid] = __expf(e1s[tid] - mxe1);
        G1s[tid] = __expf(0.01f * e1s[tid]);
    }
    __syncthreads();

    int j = tid & 255, ih = tid >> 8;
    int w5 = j >> 5, bp = j & 31;
    float e2v = g_e2[hb*M_ + j];
    float aP = 0.f, aN = 0.f;
    for (int i = ih*128; i < ih*128 + 128; i++){
        float v = e1s[i] + e2v;
        bool on = (adjs[i*8 + w5] >> bp) & 1u;
        if (on){
            if (v >= 0.f) aP += E1s[i];
            else          aN += G1s[i];
        }
    }
    pA[tid] = aP; pN[tid] = aN;
    __syncthreads();

    if (ih == 0){
        float accP = pA[j] + pA[j + 256];
        float accN = pN[j] + pN[j + 256];
        float u = mxe1 + e2v;
        float mx = fmaxf(u, 0.01f*u);
        float Fr = __expf(e2v + mxe1 - mx);
        float Gr = __expf(0.01f*e2v - mx);
        float rs = 1.f / (accP*Fr + accN*Gr);
        g_F[hb*M_ + j]  = Fr*rs*ATT_S;
        g_G2[hb*M_ + j] = Gr*rs*ATT_S;
    }
    if (tid < 256){
        g_E1[hb*M_ + tid] = E1s[tid];
        g_G1[hb*M_ + tid] = G1s[tid];
    }
}

// ---------------- k2m: HMMA attention GEMM (fp16x3), exp-free staging (R14 form) ----------------
#define OFF_A0   0          // att planes [64][40] fp16 (5120 B each)
#define OFF_A1   5120
#define OFF_B    10240      // 2 buf x 2 planes x 6656 (buf stride 13312)
#define OFF_E1   36864      // 64 f32 (raw e1 rows)
#define OFF_E2   37120      // 256 f32 (raw e2)
#define OFF_F    38144      // 256 f32
#define OFF_G2   39168      // 256 f32
#define OFF_XE1  40192      // 64 f32 (E1 row factors)
#define OFF_XG1  40448      // 64 f32 (G1 row factors)
#define OFF_ADJ  40704      // 64*8 u32
#define K2M_SMEM 42752

extern __shared__ char smm[];
__global__ __launch_bounds__(128, 4) void k2m(){
    const int b = blockIdx.x, h = blockIdx.y, ih = blockIdx.z;
    const int tid = threadIdx.x, wid = tid >> 5, lid = tid & 31;
    const int hb = h*B_ + b;
    char* sb = smm;
    unsigned sbu = s2u(smm);

    float*    e1s  = (float*)(sb + OFF_E1);
    float*    e2s  = (float*)(sb + OFF_E2);
    float*    Fs   = (float*)(sb + OFF_F);
    float*    G2s  = (float*)(sb + OFF_G2);
    float*    E1r  = (float*)(sb + OFF_XE1);
    float*    G1r  = (float*)(sb + OFF_XG1);
    unsigned* adjs = (unsigned*)(sb + OFF_ADJ);

    if (tid < 64){
        e1s[tid] = g_e1[hb*M_ + ih*64 + tid];
        E1r[tid] = g_E1[hb*M_ + ih*64 + tid];
        G1r[tid] = g_G1[hb*M_ + ih*64 + tid];
    }
    { int t2 = tid*2;
      e2s[t2] = g_e2[hb*M_ + t2];  e2s[t2+1] = g_e2[hb*M_ + t2+1];
      Fs[t2]  = g_F[hb*M_ + t2];   Fs[t2+1]  = g_F[hb*M_ + t2+1];
      G2s[t2] = g_G2[hb*M_ + t2];  G2s[t2+1] = g_G2[hb*M_ + t2+1]; }
    for (int i = tid; i < 512; i += 128) adjs[i] = g_adjb[ih*512 + i];

    // prefetch B chunk 0 (2 planes)
    {
        const char* src = (const char*)&g_Wb[0][((size_t)hb*M_)*104];
        const size_t plane_stride = (size_t)NH_*B_*M_*104*2;
        for (int idx = tid; idx < 832; idx += 128){
            int p = idx / 416, e = idx - p*416;
            cp16(sbu + OFF_B + p*6656 + e*16, src + p*plane_stride + e*16);
        }
        cp_commit();
    }
    __syncthreads();

    const int mg = wid >> 1, nh = wid & 1;
    const int colb = nh ? 56 : 0;
    const int il = tid >> 1, jb = (tid & 1) * 16;
    const float e1v = e1s[il];
    const float E1i = E1r[il];
    const float G1i = G1r[il];

    float acc[2][7][4];
    #pragma unroll
    for (int mt = 0; mt < 2; mt++)
        #pragma unroll
        for (int nt = 0; nt < 7; nt++){
            acc[mt][nt][0]=0.f; acc[mt][nt][1]=0.f; acc[mt][nt][2]=0.f; acc[mt][nt][3]=0.f;
        }

    for (int c = 0; c < 8; c++){
        const int j0 = c*32;
        // stage att planes: exp-free products
        {
            unsigned arow = adjs[il*8 + c];
            #pragma unroll
            for (int q = 0; q < 16; q += 2){
                int jg = j0 + jb + q;
                float v0 = e1v + e2s[jg];
                float v1 = e1v + e2s[jg+1];
                float p0 = (v0 >= 0.f) ? E1i*Fs[jg]   : G1i*G2s[jg];
                float p1 = (v1 >= 0.f) ? E1i*Fs[jg+1] : G1i*G2s[jg+1];
                float a0 = ((arow >> (jb+q))   & 1u) ? p0 : 0.f;
                float a1 = ((arow >> (jb+q+1)) & 1u) ? p1 : 0.f;
                __half h0,l0,h1,l1;
                hsplit(a0, h0, l0); hsplit(a1, h1, l1);
                unsigned off = (unsigned)(il*40 + jb + q)*2;
                *(unsigned*)(sb + OFF_A0 + off) = pack2h(h0, h1);
                *(unsigned*)(sb + OFF_A1 + off) = pack2h(l0, l1);
            }
        }
        if (c < 7){
            const char* src = (const char*)&g_Wb[0][((size_t)hb*M_ + (c+1)*32)*104];
            const size_t plane_stride = (size_t)NH_*B_*M_*104*2;
            unsigned dbase = sbu + OFF_B + ((c+1)&1)*13312;
            for (int idx = tid; idx < 832; idx += 128){
                int p = idx / 416, e = idx - p*416;
                cp16(dbase + p*6656 + e*16, src + p*plane_stride + e*16);
            }
            cp_commit();
            cp_wait<1>();
        } else {
            cp_wait<0>();
        }
        __syncthreads();

        unsigned bufu = sbu + OFF_B + (c&1)*13312;
        #pragma unroll
        for (int ks = 0; ks < 2; ks++){
            unsigned af[2][2][4];
            #pragma unroll
            for (int pa = 0; pa < 2; pa++)
                #pragma unroll
                for (int mt = 0; mt < 2; mt++){
                    unsigned addr = sbu + OFF_A0 + pa*5120
                        + (unsigned)((mg*32 + mt*16 + (lid & 15))*40 + ks*16 + (lid >> 4)*8)*2;
                    ldsm4(af[pa][mt], addr);
                }
            unsigned krow = (unsigned)(ks*16 + (lid & 15))*104;
            #pragma unroll
            for (int pb = 0; pb < 2; pb++){
                const int NPA = 2 - pb;
                unsigned bb = bufu + pb*6656;
                #pragma unroll
                for (int g = 0; g < 3; g++){
                    unsigned r[4];
                    ldsm4t(r, bb + (krow + colb + g*16 + (lid >> 4)*8)*2);
                    #pragma unroll
                    for (int pa = 0; pa < 2; pa++){
                        if (pa < NPA){
                            #pragma unroll
                            for (int mt = 0; mt < 2; mt++){
                                mma16816(acc[mt][2*g],     af[pa][mt], r[0], r[1]);
                                mma16816(acc[mt][2*g + 1], af[pa][mt], r[2], r[3]);
                            }
                        }
                    }
                }
                if (!nh){
                    unsigned r0, r1;
                    ldsm2t(r0, r1, bb + (krow + 48)*2);
                    #pragma unroll
                    for (int pa = 0; pa < 2; pa++){
                        if (pa < NPA){
                            #pragma unroll
                            for (int mt = 0; mt < 2; mt++)
                                mma16816(acc[mt][6], af[pa][mt], r0, r1);
                        }
                    }
                }
            }
        }
        __syncthreads();
    }

    // epilogue: unscale + elu -> g_feats
    const int NT = nh ? 6 : 7;
    int gr = lid >> 2, tg = lid & 3;
    #pragma unroll
    for (int mt = 0; mt < 2; mt++){
        size_t mrow = (size_t)b*M_ + ih*64 + mg*32 + mt*16 + gr;
        float* d0 = g_feats + mrow*300 + h*100;
        float* d1 = d0 + (size_t)8*300;
        #pragma unroll
        for (int nt = 0; nt < 7; nt++){
            if (nt >= NT) break;
            int n = colb + nt*8 + tg*2;
            if (n < 100){
                float v0 = acc[mt][nt][0]*INV_ATT; v0 = v0 > 0.f ? v0 : expm1f(v0);
                float v1 = acc[mt][nt][1]*INV_ATT; v1 = v1 > 0.f ? v1 : expm1f(v1);
                float v2 = acc[mt][nt][2]*INV_ATT; v2 = v2 > 0.f ? v2 : expm1f(v2);
                float v3 = acc[mt][nt][3]*INV_ATT; v3 = v3 > 0.f ? v3 : expm1f(v3);
                float2 p0; p0.x = v0; p0.y = v1;
                float2 p1; p1.x = v2; p1.y = v3;
                *(float2*)(d0 + n) = p0;
                *(float2*)(d1 + n) = p1;
            }
        }
    }
}

// ---------------- k3: LayerNorm(300) + elu -> x fp16 planes ----------------
__global__ __launch_bounds__(256) void k3_ln(const float* __restrict__ lnw,
                                             const float* __restrict__ lnb){
    int wid = threadIdx.x >> 5, lane = threadIdx.x & 31;
    int row = blockIdx.x*8 + wid;
    const float* xr = g_feats + (size_t)row*300;
    float v[10]; float s = 0.f;
    #pragma unroll
    for (int i = 0; i < 10; i++){
        int c = lane + i*32;
        v[i] = (c < 300) ? xr[c] : 0.f;
        s += v[i];
    }
    #pragma unroll
    for (int o = 16; o; o >>= 1) s += __shfl_xor_sync(0xffffffffu, s, o);
    float mu = s * (1.f/300.f);
    float q = 0.f;
    #pragma unroll
    for (int i = 0; i < 10; i++){
        int c = lane + i*32;
        if (c < 300){ float d = v[i] - mu; q = fmaf(d, d, q); }
    }
    #pragma unroll
    for (int o = 16; o; o >>= 1) q += __shfl_xor_sync(0xffffffffu, q, o);
    float rsv = rsqrtf(q*(1.f/300.f) + 1e-5f);
    int bb = row >> 8, mm = row & 255;
    size_t base = (size_t)bb*D2P + 100 + (size_t)mm*300;
    #pragma unroll
    for (int i = 0; i < 10; i++){
        int c = lane + i*32;
        if (c < 300){
            float t = (v[i] - mu)*rsv*__ldg(&lnw[c]) + __ldg(&lnb[c]);
            t = t > 0.f ? t : expm1f(t);
            __half th, tl; hsplit(t, th, tl);
            g_xb[0][base + c] = th;
            g_xb[1][base + c] = tl;
        }
    }
}

// ---------------- k3b: server_feat = relu(ss@W1 + b1), split-k ----------------
__global__ __launch_bounds__(256) void k3b_sfeat(const float* __restrict__ obs,
                                                 const float* __restrict__ W1,
                                                 const float* __restrict__ b1){
    __shared__ float ss[772];
    __shared__ float part[256];
    int b = blockIdx.x, tid = threadIdx.x;
    for (int i = tid; i < 770; i += 256) ss[i] = obs[(size_t)b*OBS_ + i];
    __syncthreads();
    if (tid < 200){
        int o = tid % 100, hf = tid / 100;
        int k0 = hf*385, k1 = k0 + 385;
        float a0=0.f,a1=0.f,a2=0.f,a3=0.f;
        int k = k0;
        for (; k + 4 <= k1; k += 4){
            a0 = fmaf(ss[k],   __ldg(&W1[(k)*100 + o]),   a0);
            a1 = fmaf(ss[k+1], __ldg(&W1[(k+1)*100 + o]), a1);
            a2 = fmaf(ss[k+2], __ldg(&W1[(k+2)*100 + o]), a2);
            a3 = fmaf(ss[k+3], __ldg(&W1[(k+3)*100 + o]), a3);
        }
        for (; k < k1; k++) a0 = fmaf(ss[k], __ldg(&W1[k*100 + o]), a0);
        part[tid] = (a0 + a1) + (a2 + a3);
    }
    __syncthreads();
    if (tid < 100){
        float t = fmaxf(part[tid] + part[tid + 100] + b1[tid], 0.f);
        __half th, tl; hsplit(t, th, tl);
        size_t base = (size_t)b*D2P + tid;
        g_xb[0][base] = th;
        g_xb[1][base] = tl;
    }
}

// ---------------- k4h: HMMA split-K GEMM  x @ (W2*256) (fp16x3), R14 form ----------------
#define K4H_SMEM 75776
extern __shared__ char sk4[];
__global__ __launch_bounds__(256, 2) void k4h(){
    const int kz = blockIdx.x, by = blockIdx.y;
    const int b0 = by*128;
    const int tid = threadIdx.x, wid = tid >> 5, lid = tid & 31;
    unsigned sbu = s2u(sk4);
    const int kbase = kz*544;

    const int m0 = (wid >> 1)*32, n0 = (wid & 1)*64;
    float acc[2][8][4];
    #pragma unroll
    for (int mt = 0; mt < 2; mt++)
        #pragma unroll
        for (int nt = 0; nt < 8; nt++){
            acc[mt][nt][0]=0.f; acc[mt][nt][1]=0.f; acc[mt][nt][2]=0.f; acc[mt][nt][3]=0.f;
        }

    auto stage = [&](int buf, int s){
        int kg = kbase + s*32;
        unsigned ab = sbu + buf*20480;
        #pragma unroll
        for (int i = 0; i < 8; i++){
            int q = tid + i*256;
            int p = q >> 10, rem = q & 1023;
            int row = rem >> 3, seg = rem & 7;
            cp8(ab + p*10240 + row*80 + seg*8,
                &g_xb[p][(size_t)(b0 + row)*D2P + kg + seg*4]);
        }
        unsigned bb = sbu + 40960 + buf*17408;
        #pragma unroll
        for (int i = 0; i < 4; i++){
            int q = tid + i*256;
            int p = q >> 9, rem = q & 511;
            int row = rem >> 4, seg = rem & 15;
            cp16(bb + p*8704 + row*272 + seg*16,
                 &g_W2b[p][(size_t)(kg + row)*H2_ + seg*8]);
        }
        cp_commit();
    };

    stage(0, 0);

    const int r4r = lid >> 2, c2 = (lid & 3)*2;
    for (int s = 0; s < 17; s++){
        if (s < 16) { stage((s+1)&1, s+1); cp_wait<1>(); }
        else cp_wait<0>();
        __syncthreads();

        unsigned abuf = sbu + (s&1)*20480;
        unsigned bbuf = sbu + 40960 + (s&1)*17408;
        #pragma unroll
        for (int ks = 0; ks < 2; ks++){
            unsigned af[2][2][4];
            #pragma unroll
            for (int p = 0; p < 2; p++)
                #pragma unroll
                for (int mt = 0; mt < 2; mt++){
                    unsigned addr = abuf + p*10240
                        + (unsigned)((m0 + mt*16 + (lid & 15))*40 + ks*16 + (lid >> 4)*8)*2;
                    ldsm4(af[p][mt], addr);
                }
            unsigned krow = (unsigned)(ks*16 + (lid & 15))*272 + (unsigned)(n0 + (lid >> 4)*8)*2;
            #pragma unroll
            for (int pb = 0; pb < 2; pb++){
                const int NPA = 2 - pb;
                unsigned bb = bbuf + pb*8704 + krow;
                #pragma unroll
                for (int g = 0; g < 4; g++){
                    unsigned r[4];
                    ldsm4t(r, bb + g*32);
                    #pragma unroll
                    for (int pa = 0; pa < 2; pa++){
                        if (pa < NPA){
                            #pragma unroll
                            for (int mt = 0; mt < 2; mt++){
                                mma16816(acc[mt][2*g],     af[pa][mt], r[0], r[1]);
                                mma16816(acc[mt][2*g + 1], af[pa][mt], r[2], r[3]);
                            }
                        }
                    }
                }
            }
        }
        __syncthreads();
    }

    #pragma unroll
    for (int mt = 0; mt < 2; mt++){
        int row0 = b0 + m0 + mt*16 + r4r;
        float* d0 = g_hpart + ((size_t)kz*B_ + row0)*H2_;
        float* d1 = d0 + (size_t)8*H2_;
        #pragma unroll
        for (int nt = 0; nt < 8; nt++){
            int n = n0 + nt*8 + c2;
            float2 p0; p0.x = acc[mt][nt][0]; p0.y = acc[mt][nt][1];
            float2 p1; p1.x = acc[mt][nt][2]; p1.y = acc[mt][nt][3];
            *(float2*)(d0 + n) = p0;
            *(float2*)(d1 + n) = p1;
        }
    }
}

// ---------------- k4b: split-K reduce + unscale + bias + relu ----------------
__global__ void k4b_reduce(const float* __restrict__ b2){
    int t = blockIdx.x*blockDim.x + threadIdx.x;
    if (t >= B_*H2_) return;
    int b = t >> 7, n = t & 127;
    float s = 0.f;
    for (int kz = 0; kz < KSPL; kz++) s += g_hpart[((size_t)kz*B_ + b)*H2_ + n];
    g_hidT[n*B_ + b] = fmaxf(s*INV_W2 + b2[n], 0.f);
}

// ---------------- k5: logits + gumbel + argmax + one-hot write ----------------
__global__ __launch_bounds__(256) void k5_logits(const float* __restrict__ Wout,
                                                 const float* __restrict__ bout,
                                                 const float* __restrict__ ug,
                                                 float* __restrict__ out){
    __shared__ __align__(16) float Wos[H2_*36];
    __shared__ float bos[A_];
    int mb = blockIdx.x, b = threadIdx.x;
    for (int i = threadIdx.x; i < H2_*36; i += 256){
        int hh = i / 36, aa = i - hh*36;
        Wos[i] = (aa < A_) ? Wout[(size_t)mb*H2_*A_ + hh*A_ + aa] : 0.f;
    }
    if (threadIdx.x < A_) bos[threadIdx.x] = bout[mb*A_ + threadIdx.x];
    __syncthreads();

    unsigned wou = s2u(Wos);
    unsigned long long acc[17];
    #pragma unroll
    for (int p = 0; p < 17; p++) acc[p] = 0ull;
    #pragma unroll 2
    for (int hh = 0; hh < H2_; hh++){
        float hv = g_hidT[hh*B_ + b];
        unsigned long long hs = splat2(hv);
        unsigned base = wou + hh*144;
        #pragma unroll
        for (int q = 0; q < 8; q++){
            unsigned long long w0, w1; lds_v2u64(base + q*16, w0, w1);
            fma2(acc[2*q],   hs, w0);
            fma2(acc[2*q+1], hs, w1);
        }
        fma2(acc[16], hs, lds_u64(base + 128));
    }

    const float* u = ug + ((size_t)b*M_ + mb)*A_;
    float best = -INFINITY; int bi = 0;
    #pragma unroll
    for (int p = 0; p < 17; p++){
        float va, vb; unpk(acc[p], va, vb);
        #pragma unroll
        for (int s = 0; s < 2; s++){
            int a = 2*p + s;
            if (a >= A_) break;
            float x = (s ? vb : va) + bos[a];
            float e = x > 0.f ? x : expm1f(x);
            float l = tanhf(e);
            float uu = fmaxf(__ldg(&u[a]), 1e-10f);
            float g = -logf(-logf(uu));
            float z = l + g;
            if (z > best){ best = z; bi = a; }
        }
    }
    float* orow = out + ((size_t)b*M_ + mb)*A_;
    #pragma unroll
    for (int a = 0; a < A_; a++) orow[a] = (a == bi) ? 1.f : 0.f;
}

extern "C" void kernel_launch(void* const* d_in, const int* in_sizes, int n_in,
                              void* d_out, int out_size){
    const float* obs  = (const float*)d_in[0];
    const int*   adj  = (const int*)  d_in[1];
    const float* ug   = (const float*)d_in[2];
    const float* Wg   = (const float*)d_in[3];
    const float* ag   = (const float*)d_in[4];
    const float* lnw  = (const float*)d_in[5];
    const float* lnb  = (const float*)d_in[6];
    const float* W1   = (const float*)d_in[7];
    const float* b1   = (const float*)d_in[8];
    const float* W2   = (const float*)d_in[9];
    const float* b2   = (const float*)d_in[10];
    const float* Wout = (const float*)d_in[11];
    const float* bout = (const float*)d_in[12];
    float* out = (float*)d_out;

    k0_adjbits<<<M_, 256>>>(adj);
    k_w2s<<<(int)(((size_t)D2P*H2_/4 + 255)/256), 256>>>(W2);
    k1_wh<<<dim3(B_, NH_), 256>>>(obs, Wg, ag);
    k1b_stats<<<dim3(B_, NH_), 512>>>();

    cudaFuncSetAttribute(k2m, cudaFuncAttributeMaxDynamicSharedMemorySize, K2M_SMEM);
    k2m<<<dim3(B_, NH_, 4), 128, K2M_SMEM>>>();

    k3b_sfeat<<<B_, 256>>>(obs, W1, b1);
    k3_ln<<<(B_*M_)/8, 256>>>(lnw, lnb);

    cudaFuncSetAttribute(k4h, cudaFuncAttributeMaxDynamicSharedMemorySize, K4H_SMEM);
    k4h<<<dim3(KSPL, 2), 256, K4H_SMEM>>>();

    k4b_reduce<<<(B_*H2_ + 255)/256, 256>>>(b2);
    k5_logits<<<M_, 256>>>(Wout, bout, ug, out);
}